// round 1
// baseline (speedup 1.0000x reference)
#include <cuda_runtime.h>
#include <math.h>

// Problem constants
#define NPARTS   2
#define NFULL    24576
#define M        8192          // NFULL / SAMPLE_STEP
#define DIRS     2

// Chamfer tiling
#define TPB      256
#define IPT      4             // i-points per thread
#define IBLK     (TPB*IPT)     // 1024 i per block
#define JBLK     1024          // j tile in smem
#define NIB      (M/IBLK)      // 8
#define NJB      (M/JBLK)      // 8
#define NBLOCKS  (DIRS*NPARTS*NIB*NJB)  // 256

// Scratch (allocation-free: __device__ globals)
__device__ float4 g_x[2][NPARTS][M];          // [set][part][m]: (x,y,z,|x|^2)   set0=transformed cad, set1=sampled cam
__device__ float4 g_y[2][NPARTS][M];          // [set][part][m]: (-2x,-2y,-2z,|x|^2)
__device__ unsigned int g_min[DIRS][NPARTS][M]; // min d2 as uint bit-pattern (nonneg floats)
__device__ float g_T[NPARTS][16];
__device__ float g_sums[4];                   // [dir*2+part] = sum_i sqrt(min d2)
__device__ float g_ekin;

// ---------------------------------------------------------------------------
// Kernel 0: transforms + e_kin (tiny)
// ---------------------------------------------------------------------------
__global__ void k_setup(const float* __restrict__ rot_quat,
                        const float* __restrict__ tra,
                        const float* __restrict__ joint_axes,
                        float* __restrict__ out, int out_size) {
    int tid = threadIdx.x;
    // zero any tail of the output beyond the 34 floats we own
    for (int i = 34 + tid; i < out_size; i += blockDim.x) out[i] = 0.0f;

    if (tid != 0) return;

    float T[2][16];
    for (int p = 0; p < 2; p++) {
        const float* q = rot_quat + 4 * p;
        float n = sqrtf(q[0]*q[0] + q[1]*q[1] + q[2]*q[2] + q[3]*q[3]);
        float a = q[0]/n, b = q[1]/n, c = q[2]/n, d = q[3]/n;
        float R[9] = {
            1.f - 2.f*c*c - 2.f*d*d,  2.f*b*c - 2.f*a*d,        2.f*a*c + 2.f*b*d,
            2.f*b*c + 2.f*a*d,        1.f - 2.f*b*b - 2.f*d*d,  2.f*c*d - 2.f*a*b,
            2.f*b*d - 2.f*a*c,        2.f*a*b + 2.f*c*d,        1.f - 2.f*b*b - 2.f*c*c
        };
        for (int r = 0; r < 3; r++) {
            for (int cc = 0; cc < 3; cc++) T[p][r*4+cc] = R[r*3+cc];
            T[p][r*4+3] = tra[p*3 + r];
        }
        T[p][12] = 0.f; T[p][13] = 0.f; T[p][14] = 0.f; T[p][15] = 1.f;
        for (int i = 0; i < 16; i++) {
            g_T[p][i] = T[p][i];
            out[2 + p*16 + i] = T[p][i];
        }
    }
    // e_kin = sigmoid(-5 * || T0 @ J0^T - T1 @ J1^T ||_F)
    float ss = 0.f;
    for (int r = 0; r < 4; r++) {
        for (int c2 = 0; c2 < 2; c2++) {
            float v0 = 0.f, v1 = 0.f;
            for (int k = 0; k < 4; k++) {
                v0 += T[0][r*4+k] * joint_axes[0*8 + c2*4 + k];
                v1 += T[1][r*4+k] * joint_axes[1*8 + c2*4 + k];
            }
            float dd = v0 - v1;
            ss += dd * dd;
        }
    }
    float nrm = sqrtf(ss);
    float ek = 1.f / (1.f + expf(5.f * nrm));
    g_ekin = ek;
    out[1] = ek;
}

// ---------------------------------------------------------------------------
// Kernel 1: sample + transform + pack points, init min arrays
// launch exactly 32768 threads (128 x 256)
// ---------------------------------------------------------------------------
__global__ void k_pack(const float* __restrict__ cam,
                       const float* __restrict__ cad) {
    int idx = blockIdx.x * blockDim.x + threadIdx.x;   // 0..32767
    // init min arrays to +inf bit pattern (DIRS*NPARTS*M = 32768 entries)
    ((unsigned int*)g_min)[idx] = 0x7f800000u;

    if (idx < NPARTS * M) {
        int p = idx >> 13;
        int m = idx & (M - 1);
        long off = ((long)p * NFULL + 3L * m) * 3L;

        // transformed cad point
        const float* cp = cad + off;
        float x = cp[0], y = cp[1], z = cp[2];
        const float* T = g_T[p];
        float tx = T[0]*x + T[1]*y + T[2]*z  + T[3];
        float ty = T[4]*x + T[5]*y + T[6]*z  + T[7];
        float tz = T[8]*x + T[9]*y + T[10]*z + T[11];
        float n2 = tx*tx + ty*ty + tz*tz;
        g_x[0][p][m] = make_float4(tx, ty, tz, n2);
        g_y[0][p][m] = make_float4(-2.f*tx, -2.f*ty, -2.f*tz, n2);

        // sampled camera point
        const float* qp = cam + off;
        float cx = qp[0], cy = qp[1], cz = qp[2];
        float cn2 = cx*cx + cy*cy + cz*cz;
        g_x[1][p][m] = make_float4(cx, cy, cz, cn2);
        g_y[1][p][m] = make_float4(-2.f*cx, -2.f*cy, -2.f*cz, cn2);
    }
}

// ---------------------------------------------------------------------------
// Kernel 2: brute-force min-d2, both directions. FMA-bound.
//   dir 0: X = transformed cad, Y = cam   -> min over cam per cad row
//   dir 1: X = cam, Y = transformed cad   -> min over cad per cam row
// ---------------------------------------------------------------------------
__global__ __launch_bounds__(TPB) void k_chamfer() {
    __shared__ float4 tile[JBLK];

    int b    = blockIdx.x;
    int jb   = b & (NJB - 1);
    int ib   = (b >> 3) & (NIB - 1);
    int pd   = b >> 6;             // 0..3
    int part = pd & 1;
    int dir  = pd >> 1;

    const float4* __restrict__ X = g_x[dir][part];
    const float4* __restrict__ Y = g_y[dir ^ 1][part];
    unsigned int* __restrict__ out = g_min[dir][part];

    int tid = threadIdx.x;
    int i0  = ib * IBLK + tid;

    float xr[IPT][3], sx[IPT], rmin[IPT];
    #pragma unroll
    for (int k = 0; k < IPT; k++) {
        float4 v = X[i0 + k * TPB];
        xr[k][0] = v.x; xr[k][1] = v.y; xr[k][2] = v.z;
        sx[k] = v.w;
        rmin[k] = __int_as_float(0x7f800000);
    }

    int j0 = jb * JBLK;
    for (int t = tid; t < JBLK; t += TPB) tile[t] = Y[j0 + t];
    __syncthreads();

    #pragma unroll 4
    for (int j = 0; j < JBLK; j++) {
        float4 y = tile[j];   // LDS.128 broadcast, conflict-free
        #pragma unroll
        for (int k = 0; k < IPT; k++) {
            // r = |y|^2 - 2 x.y    (3 FFMA: y pre-scaled by -2, w = |y|^2)
            float r = fmaf(y.x, xr[k][0],
                      fmaf(y.y, xr[k][1],
                      fmaf(y.z, xr[k][2], y.w)));
            rmin[k] = fminf(rmin[k], r);
        }
    }

    #pragma unroll
    for (int k = 0; k < IPT; k++) {
        // full d2 = rmin + |x|^2, clamped nonneg -> uint atomicMin is order-correct
        float v = fmaxf(rmin[k] + sx[k], 0.0f);
        atomicMin(&out[i0 + k * TPB], __float_as_uint(v));
    }
}

// ---------------------------------------------------------------------------
// Kernel 3: per-(dir,part) sum of sqrt(min d2)
// ---------------------------------------------------------------------------
__global__ void k_reduce() {
    __shared__ float sh[256];
    int pd = blockIdx.x;                   // 0..3, dir = pd>>1, part = pd&1
    const unsigned int* __restrict__ mv = g_min[pd >> 1][pd & 1];
    float s = 0.f;
    for (int i = threadIdx.x; i < M; i += 256)
        s += sqrtf(__uint_as_float(mv[i]));
    sh[threadIdx.x] = s;
    __syncthreads();
    for (int o = 128; o > 0; o >>= 1) {
        if (threadIdx.x < o) sh[threadIdx.x] += sh[threadIdx.x + o];
        __syncthreads();
    }
    if (threadIdx.x == 0) g_sums[pd] = sh[0];
}

// ---------------------------------------------------------------------------
// Kernel 4: final objective
// ---------------------------------------------------------------------------
__global__ void k_final(const float* __restrict__ w, float* __restrict__ out) {
    if (threadIdx.x == 0 && blockIdx.x == 0) {
        float eg = 0.f;
        for (int p = 0; p < 2; p++)
            eg += w[p] * ((g_sums[p] + g_sums[2 + p]) * (1.0f / (float)M));
        out[0] = eg + w[NPARTS] * g_ekin;
    }
}

// ---------------------------------------------------------------------------
extern "C" void kernel_launch(void* const* d_in, const int* in_sizes, int n_in,
                              void* d_out, int out_size) {
    const float* cam  = (const float*)d_in[0];  // camera_pts (2,24576,3)
    const float* cad  = (const float*)d_in[1];  // cad_pts    (2,24576,3)
    const float* w    = (const float*)d_in[2];  // part_weight (3,)
    const float* quat = (const float*)d_in[3];  // rot_quat   (2,4)
    const float* tra  = (const float*)d_in[4];  // tra        (2,3,1)
    const float* jax_ = (const float*)d_in[5];  // joint_axes (2,2,4)
    float* out = (float*)d_out;

    k_setup<<<1, 32>>>(quat, tra, jax_, out, out_size);
    k_pack<<<128, 256>>>(cam, cad);
    k_chamfer<<<NBLOCKS, TPB>>>();
    k_reduce<<<4, 256>>>();
    k_final<<<1, 32>>>(w, out);
}

// round 2
// speedup vs baseline: 1.1051x; 1.1051x over previous
#include <cuda_runtime.h>
#include <math.h>

// Problem constants
#define NPARTS   2
#define NFULL    24576
#define M        8192          // NFULL / SAMPLE_STEP
#define DIRS     2

// Chamfer tiling
#define TPB      256
#define IPT      4             // i-points per thread
#define IBLK     (TPB*IPT)     // 1024 i per block
#define JBLK     1024          // j tile (elements) in smem
#define JP       (JBLK/2)      // j-pairs per tile
#define NIB      (M/IBLK)      // 8
#define NJB      (M/JBLK)      // 8
#define NBLOCKS  (DIRS*NPARTS*NIB*NJB)  // 256

typedef unsigned long long ull;

// Scratch (allocation-free: __device__ globals)
__device__ float4 g_x[2][NPARTS][M];            // [set][part][m]: (x,y,z,|x|^2)
__device__ float4 g_ypA[2][NPARTS][M/2];        // j-pair packed: (-2x0,-2x1,-2y0,-2y1)
__device__ float4 g_ypB[2][NPARTS][M/2];        // j-pair packed: (-2z0,-2z1,|y0|^2,|y1|^2)
__device__ unsigned int g_min[DIRS][NPARTS][M]; // min d2 bit-pattern (nonneg floats)
__device__ float g_T[NPARTS][16];
__device__ float g_sums[4];                     // [dir*2+part] = sum_i sqrt(min d2)
__device__ float g_ekin;

// ---- f32x2 helpers ---------------------------------------------------------
__device__ __forceinline__ ull pack2(float lo, float hi) {
    ull r; asm("mov.b64 %0, {%1,%2};" : "=l"(r) : "f"(lo), "f"(hi)); return r;
}
__device__ __forceinline__ ull fma2(ull a, ull b, ull c) {
    ull d; asm("fma.rn.f32x2 %0, %1, %2, %3;" : "=l"(d) : "l"(a), "l"(b), "l"(c)); return d;
}
__device__ __forceinline__ void unpack2(ull v, float& lo, float& hi) {
    asm("mov.b64 {%0,%1}, %2;" : "=f"(lo), "=f"(hi) : "l"(v));
}

// ---------------------------------------------------------------------------
// Kernel 0: transforms + e_kin (tiny)
// ---------------------------------------------------------------------------
__global__ void k_setup(const float* __restrict__ rot_quat,
                        const float* __restrict__ tra,
                        const float* __restrict__ joint_axes,
                        float* __restrict__ out, int out_size) {
    int tid = threadIdx.x;
    for (int i = 34 + tid; i < out_size; i += blockDim.x) out[i] = 0.0f;
    if (tid != 0) return;

    float T[2][16];
    for (int p = 0; p < 2; p++) {
        const float* q = rot_quat + 4 * p;
        float n = sqrtf(q[0]*q[0] + q[1]*q[1] + q[2]*q[2] + q[3]*q[3]);
        float a = q[0]/n, b = q[1]/n, c = q[2]/n, d = q[3]/n;
        float R[9] = {
            1.f - 2.f*c*c - 2.f*d*d,  2.f*b*c - 2.f*a*d,        2.f*a*c + 2.f*b*d,
            2.f*b*c + 2.f*a*d,        1.f - 2.f*b*b - 2.f*d*d,  2.f*c*d - 2.f*a*b,
            2.f*b*d - 2.f*a*c,        2.f*a*b + 2.f*c*d,        1.f - 2.f*b*b - 2.f*c*c
        };
        for (int r = 0; r < 3; r++) {
            for (int cc = 0; cc < 3; cc++) T[p][r*4+cc] = R[r*3+cc];
            T[p][r*4+3] = tra[p*3 + r];
        }
        T[p][12] = 0.f; T[p][13] = 0.f; T[p][14] = 0.f; T[p][15] = 1.f;
        for (int i = 0; i < 16; i++) {
            g_T[p][i] = T[p][i];
            out[2 + p*16 + i] = T[p][i];
        }
    }
    float ss = 0.f;
    for (int r = 0; r < 4; r++) {
        for (int c2 = 0; c2 < 2; c2++) {
            float v0 = 0.f, v1 = 0.f;
            for (int k = 0; k < 4; k++) {
                v0 += T[0][r*4+k] * joint_axes[0*8 + c2*4 + k];
                v1 += T[1][r*4+k] * joint_axes[1*8 + c2*4 + k];
            }
            float dd = v0 - v1;
            ss += dd * dd;
        }
    }
    float ek = 1.f / (1.f + expf(5.f * sqrtf(ss)));
    g_ekin = ek;
    out[1] = ek;
}

// ---------------------------------------------------------------------------
// Kernel 1: sample + transform + pack points, init min arrays + sums
// launch exactly 32768 threads (128 x 256)
// ---------------------------------------------------------------------------
__global__ void k_pack(const float* __restrict__ cam,
                       const float* __restrict__ cad) {
    int idx = blockIdx.x * blockDim.x + threadIdx.x;   // 0..32767
    ((unsigned int*)g_min)[idx] = 0x7f800000u;
    if (idx < 4) g_sums[idx] = 0.0f;

    if (idx < NPARTS * M) {
        int p = idx >> 13;
        int m = idx & (M - 1);
        long off = ((long)p * NFULL + 3L * m) * 3L;
        int jp = m >> 1, o = m & 1;

        // transformed cad point  (set 0)
        const float* cp = cad + off;
        float x = cp[0], y = cp[1], z = cp[2];
        const float* T = g_T[p];
        float tx = T[0]*x + T[1]*y + T[2]*z  + T[3];
        float ty = T[4]*x + T[5]*y + T[6]*z  + T[7];
        float tz = T[8]*x + T[9]*y + T[10]*z + T[11];
        float n2 = tx*tx + ty*ty + tz*tz;
        g_x[0][p][m] = make_float4(tx, ty, tz, n2);
        {
            float* A = (float*)&g_ypA[0][p][jp];
            float* B = (float*)&g_ypB[0][p][jp];
            A[o] = -2.f*tx; A[2+o] = -2.f*ty;
            B[o] = -2.f*tz; B[2+o] = n2;
        }

        // sampled camera point   (set 1)
        const float* qp = cam + off;
        float cx = qp[0], cy = qp[1], cz = qp[2];
        float cn2 = cx*cx + cy*cy + cz*cz;
        g_x[1][p][m] = make_float4(cx, cy, cz, cn2);
        {
            float* A = (float*)&g_ypA[1][p][jp];
            float* B = (float*)&g_ypB[1][p][jp];
            A[o] = -2.f*cx; A[2+o] = -2.f*cy;
            B[o] = -2.f*cz; B[2+o] = cn2;
        }
    }
}

// ---------------------------------------------------------------------------
// Kernel 2: brute-force min-d2 via packed f32x2 FMA. FMA-pipe-bound.
//   dir 0: X = transformed cad, Y = cam ; dir 1: swapped
// ---------------------------------------------------------------------------
__global__ __launch_bounds__(TPB) void k_chamfer() {
    __shared__ float4 tA[JP];
    __shared__ float4 tB[JP];

    int b    = blockIdx.x;
    int jb   = b & (NJB - 1);
    int ib   = (b >> 3) & (NIB - 1);
    int pd   = b >> 6;             // 0..3
    int part = pd & 1;
    int dir  = pd >> 1;

    const float4* __restrict__ X  = g_x[dir][part];
    const float4* __restrict__ YA = g_ypA[dir ^ 1][part];
    const float4* __restrict__ YB = g_ypB[dir ^ 1][part];
    unsigned int* __restrict__ out = g_min[dir][part];

    int tid = threadIdx.x;
    int i0  = ib * IBLK + tid;

    ull xx[IPT], xy[IPT], xz[IPT];
    float sx[IPT], rmA[IPT], rmB[IPT];
    #pragma unroll
    for (int k = 0; k < IPT; k++) {
        float4 v = X[i0 + k * TPB];
        xx[k] = pack2(v.x, v.x);
        xy[k] = pack2(v.y, v.y);
        xz[k] = pack2(v.z, v.z);
        sx[k] = v.w;
        rmA[k] = __int_as_float(0x7f800000);
        rmB[k] = __int_as_float(0x7f800000);
    }

    int jp0 = jb * JP;
    for (int t = tid; t < JP; t += TPB) {
        tA[t] = YA[jp0 + t];
        tB[t] = YB[jp0 + t];
    }
    __syncthreads();

    #pragma unroll 4
    for (int jp = 0; jp < JP; jp++) {
        float4 a = tA[jp];               // (-2x0,-2x1,-2y0,-2y1)
        float4 b4 = tB[jp];              // (-2z0,-2z1, n0, n1)
        ull yx = pack2(a.x,  a.y);
        ull yy = pack2(a.z,  a.w);
        ull yz = pack2(b4.x, b4.y);
        ull yw = pack2(b4.z, b4.w);
        #pragma unroll
        for (int k = 0; k < IPT; k++) {
            // r2 = n - 2 x.y  for both j of the pair (3 FFMA2)
            ull r2 = fma2(yx, xx[k], fma2(yy, xy[k], fma2(yz, xz[k], yw)));
            float lo, hi; unpack2(r2, lo, hi);
            rmA[k] = fminf(rmA[k], lo);
            rmB[k] = fminf(rmB[k], hi);
        }
    }

    #pragma unroll
    for (int k = 0; k < IPT; k++) {
        float v = fmaxf(fminf(rmA[k], rmB[k]) + sx[k], 0.0f);
        atomicMin(&out[i0 + k * TPB], __float_as_uint(v));
    }
}

// ---------------------------------------------------------------------------
// Kernel 3: sum of sqrt(min d2) — 32 blocks (8 chunks x 4 pd), atomicAdd
// ---------------------------------------------------------------------------
__global__ void k_reduce() {
    int pd    = blockIdx.x >> 3;           // 0..3
    int chunk = blockIdx.x & 7;            // 0..7
    const unsigned int* __restrict__ mv = g_min[pd >> 1][pd & 1] + chunk * 1024;
    float s = 0.f;
    #pragma unroll
    for (int r = 0; r < 4; r++)
        s += sqrtf(__uint_as_float(mv[threadIdx.x + r * 256]));
    // warp reduce
    #pragma unroll
    for (int o = 16; o > 0; o >>= 1)
        s += __shfl_xor_sync(0xffffffffu, s, o);
    __shared__ float sh[8];
    if ((threadIdx.x & 31) == 0) sh[threadIdx.x >> 5] = s;
    __syncthreads();
    if (threadIdx.x < 8) {
        float v = sh[threadIdx.x];
        #pragma unroll
        for (int o = 4; o > 0; o >>= 1)
            v += __shfl_xor_sync(0xffu, v, o);
        if (threadIdx.x == 0) atomicAdd(&g_sums[pd], v);
    }
}

// ---------------------------------------------------------------------------
// Kernel 4: final objective
// ---------------------------------------------------------------------------
__global__ void k_final(const float* __restrict__ w, float* __restrict__ out) {
    if (threadIdx.x == 0 && blockIdx.x == 0) {
        float eg = 0.f;
        for (int p = 0; p < 2; p++)
            eg += w[p] * ((g_sums[p] + g_sums[2 + p]) * (1.0f / (float)M));
        out[0] = eg + w[NPARTS] * g_ekin;
    }
}

// ---------------------------------------------------------------------------
extern "C" void kernel_launch(void* const* d_in, const int* in_sizes, int n_in,
                              void* d_out, int out_size) {
    const float* cam  = (const float*)d_in[0];
    const float* cad  = (const float*)d_in[1];
    const float* w    = (const float*)d_in[2];
    const float* quat = (const float*)d_in[3];
    const float* tra  = (const float*)d_in[4];
    const float* jax_ = (const float*)d_in[5];
    float* out = (float*)d_out;

    k_setup<<<1, 32>>>(quat, tra, jax_, out, out_size);
    k_pack<<<128, 256>>>(cam, cad);
    k_chamfer<<<NBLOCKS, TPB>>>();
    k_reduce<<<32, 256>>>();
    k_final<<<1, 32>>>(w, out);
}

// round 4
// speedup vs baseline: 1.2404x; 1.1224x over previous
#include <cuda_runtime.h>
#include <math.h>

// Problem constants
#define NPARTS   2
#define NFULL    24576
#define M        8192          // NFULL / SAMPLE_STEP
#define SCALE    (1.0f/8192.0f)

// Chamfer tiling: tile 1024i x 1024j, grid = 2 parts x 8 ib x 8 jb = 128
#define TPB      256
#define IPT      32            // i-points per thread (warp covers 32*32 = 1024 i)
#define TILE     1024
#define NB       8
#define NBLOCKS  (NPARTS*NB*NB)

// Scratch (allocation-free: __device__ globals)
__device__ float4 g_x[NPARTS][M];            // transformed cad: (x, y, z, |x|^2)
__device__ float4 g_y[NPARTS][M];            // cam: (-2x, -2y, -2z, |y|^2)
__device__ unsigned int g_rowmin[NPARTS][M]; // min_j d2 (uint bit pattern, nonneg)
__device__ unsigned int g_colmin[NPARTS][M]; // min_i d2
__device__ float g_sums[4];                  // [0,1]=row sums p0,p1  [2,3]=col sums

// ---------------------------------------------------------------------------
// Transform helper: quat+tra -> 3x4 (rows of R | t)
// ---------------------------------------------------------------------------
__device__ __forceinline__ void make_T(const float* __restrict__ q4,
                                       const float* __restrict__ t3, float* T) {
    float n = sqrtf(q4[0]*q4[0] + q4[1]*q4[1] + q4[2]*q4[2] + q4[3]*q4[3]);
    float a = q4[0]/n, b = q4[1]/n, c = q4[2]/n, d = q4[3]/n;
    T[0] = 1.f - 2.f*c*c - 2.f*d*d; T[1] = 2.f*b*c - 2.f*a*d;       T[2]  = 2.f*a*c + 2.f*b*d;       T[3]  = t3[0];
    T[4] = 2.f*b*c + 2.f*a*d;       T[5] = 1.f - 2.f*b*b - 2.f*d*d; T[6]  = 2.f*c*d - 2.f*a*b;       T[7]  = t3[1];
    T[8] = 2.f*b*d - 2.f*a*c;       T[9] = 2.f*a*b + 2.f*c*d;       T[10] = 1.f - 2.f*b*b - 2.f*c*c; T[11] = t3[2];
}

// ---------------------------------------------------------------------------
// Kernel 1: pack points + init min arrays + zero sums. 128x256 = 32768 threads
// ---------------------------------------------------------------------------
__global__ void k_pack(const float* __restrict__ cam,
                       const float* __restrict__ cad,
                       const float* __restrict__ quat,
                       const float* __restrict__ tra) {
    int idx = blockIdx.x * blockDim.x + threadIdx.x;   // 0..32767
    if (idx < NPARTS * M) ((unsigned int*)g_rowmin)[idx] = 0x7f800000u;
    else                  ((unsigned int*)g_colmin)[idx - NPARTS*M] = 0x7f800000u;
    if (idx < 4) g_sums[idx] = 0.0f;

    if (idx < NPARTS * M) {
        int p = idx >> 13;
        int m = idx & (M - 1);
        long off = ((long)p * NFULL + 3L * m) * 3L;

        float T[12];
        make_T(quat + 4*p, tra + 3*p, T);

        // transformed cad point -> X side (rows)
        const float* cp = cad + off;
        float x = cp[0], y = cp[1], z = cp[2];
        float tx = T[0]*x + T[1]*y + T[2]*z  + T[3];
        float ty = T[4]*x + T[5]*y + T[6]*z  + T[7];
        float tz = T[8]*x + T[9]*y + T[10]*z + T[11];
        float n2 = tx*tx + ty*ty + tz*tz;
        g_x[p][m] = make_float4(tx, ty, tz, n2);

        // camera point -> Y side (cols), prescaled by -2
        const float* qp = cam + off;
        float cx = qp[0], cy = qp[1], cz = qp[2];
        float cn2 = cx*cx + cy*cy + cz*cz;
        g_y[p][m] = make_float4(-2.f*cx, -2.f*cy, -2.f*cz, cn2);
    }
}

// ---------------------------------------------------------------------------
// Kernel 2: fused chamfer — one pass over D computes BOTH direction minima.
//   s   = -2 x.y + |x|^2      (3-FFMA chain, per-i addend innermost)
//   row: min_j (s + n_j)       col: n_j + min_i s
// Each warp covers all 1024 i of the block tile (32 i/thread) and a disjoint
// 1/8 of the j's, so col-min completes within one warp (shfl reduce).
// ---------------------------------------------------------------------------
__global__ __launch_bounds__(TPB) void k_chamfer() {
    __shared__ float4 ytile[TILE];
    __shared__ unsigned int rowred[TILE];

    int b    = blockIdx.x;
    int jb   = b & (NB - 1);
    int ib   = (b >> 3) & (NB - 1);
    int part = b >> 6;

    const float4* __restrict__ X = g_x[part];
    const float4* __restrict__ Y = g_y[part];

    int tid  = threadIdx.x;
    int w    = tid >> 5;
    int lane = tid & 31;

    // load this thread's 32 i-points into registers
    float xr[IPT], yr[IPT], zr[IPT], sr[IPT], row[IPT];
    int ibase = ib * TILE;
    #pragma unroll
    for (int k = 0; k < IPT; k++) {
        float4 v = X[ibase + k * 32 + lane];
        xr[k] = v.x; yr[k] = v.y; zr[k] = v.z; sr[k] = v.w;
        row[k] = __int_as_float(0x7f800000);
    }

    // stage j tile + init row merge array
    int jbase = jb * TILE;
    for (int t = tid; t < TILE; t += TPB) {
        ytile[t]  = Y[jbase + t];
        rowred[t] = 0x7f800000u;
    }
    __syncthreads();

    // sweep this warp's 128 j's
    for (int m = 0; m < TILE / 8; m++) {
        int jl = w + 8 * m;
        float4 y4 = ytile[jl];            // broadcast LDS.128, conflict-free
        float col = __int_as_float(0x7f800000);
        #pragma unroll
        for (int k = 0; k < IPT; k++) {
            float s = fmaf(y4.x, xr[k],
                      fmaf(y4.y, yr[k],
                      fmaf(y4.z, zr[k], sr[k])));   // -2x.y + |x|^2
            row[k] = fminf(row[k], s + y4.w);        // + |y|^2 = full d2
            col    = fminf(col, s);
        }
        // col-min across 32 lanes (covers all 1024 i of the tile)
        #pragma unroll
        for (int o = 16; o > 0; o >>= 1)
            col = fminf(col, __shfl_xor_sync(0xffffffffu, col, o));
        if (lane == 0) {
            float v = fmaxf(col + y4.w, 0.0f);
            atomicMin(&g_colmin[part][jbase + jl], __float_as_uint(v));
        }
    }

    // merge row partials across the 8 warps via smem uint atomicMin
    #pragma unroll
    for (int k = 0; k < IPT; k++) {
        float v = fmaxf(row[k], 0.0f);
        atomicMin(&rowred[k * 32 + lane], __float_as_uint(v));
    }
    __syncthreads();

    #pragma unroll
    for (int sft = 0; sft < TILE / TPB; sft++) {
        int il = tid + sft * TPB;
        atomicMin(&g_rowmin[part][ibase + il], rowred[il]);
    }
}

// ---------------------------------------------------------------------------
// Kernel 3: sum of sqrt(min d2) — 32 blocks, atomicAdd partials
// ---------------------------------------------------------------------------
__global__ void k_reduce() {
    int bi    = blockIdx.x;
    int sidx  = bi >> 3;                  // 0..3
    int p     = sidx & 1;
    int chunk = bi & 7;
    const unsigned int* __restrict__ mv =
        ((bi < 16) ? g_rowmin[p] : g_colmin[p]) + chunk * 1024;
    float s = 0.f;
    #pragma unroll
    for (int r = 0; r < 4; r++)
        s += sqrtf(__uint_as_float(mv[threadIdx.x + r * 256]));
    #pragma unroll
    for (int o = 16; o > 0; o >>= 1)
        s += __shfl_xor_sync(0xffffffffu, s, o);
    __shared__ float sh[8];
    if ((threadIdx.x & 31) == 0) sh[threadIdx.x >> 5] = s;
    __syncthreads();
    if (threadIdx.x < 8) {
        float v = sh[threadIdx.x];
        #pragma unroll
        for (int o = 4; o > 0; o >>= 1)
            v += __shfl_xor_sync(0xffu, v, o);
        if (threadIdx.x == 0) atomicAdd(&g_sums[sidx], v);
    }
}

// ---------------------------------------------------------------------------
// Kernel 4: transforms/e_kin/objective -> out  (also zeroes any out tail)
//   e_kin uses the FULL 4x4 transforms: rows 0..2 from T, plus row 3 =
//   (0,0,0,1), whose contribution is (J0[c][3] - J1[c][3])^2 per column
//   (the joint axes differ between parts — row 3 does NOT cancel).
// ---------------------------------------------------------------------------
__global__ void k_final(const float* __restrict__ w,
                        const float* __restrict__ quat,
                        const float* __restrict__ tra,
                        const float* __restrict__ joint_axes,
                        float* __restrict__ out, int out_size) {
    int tid = threadIdx.x;
    for (int i = 34 + tid; i < out_size; i += blockDim.x) out[i] = 0.0f;
    if (tid != 0) return;

    float T[2][12];
    for (int p = 0; p < 2; p++) {
        make_T(quat + 4*p, tra + 3*p, T[p]);
        for (int r = 0; r < 3; r++) {
            for (int c = 0; c < 4; c++) out[2 + p*16 + r*4 + c] = T[p][r*4 + c];
        }
        out[2 + p*16 + 12] = 0.f; out[2 + p*16 + 13] = 0.f;
        out[2 + p*16 + 14] = 0.f; out[2 + p*16 + 15] = 1.f;
    }
    float ss = 0.f;
    for (int c2 = 0; c2 < 2; c2++) {
        for (int r = 0; r < 3; r++) {
            float v0 = 0.f, v1 = 0.f;
            for (int k = 0; k < 4; k++) {
                v0 += T[0][r*4+k] * joint_axes[0*8 + c2*4 + k];
                v1 += T[1][r*4+k] * joint_axes[1*8 + c2*4 + k];
            }
            float dd = v0 - v1;
            ss += dd * dd;
        }
        // row 3 contribution: (0,0,0,1)·J0[c2] - (0,0,0,1)·J1[c2]
        float d3 = joint_axes[0*8 + c2*4 + 3] - joint_axes[1*8 + c2*4 + 3];
        ss += d3 * d3;
    }
    float ek = 1.f / (1.f + expf(5.f * sqrtf(ss)));
    out[1] = ek;

    float eg = 0.f;
    for (int p = 0; p < 2; p++)
        eg += w[p] * ((g_sums[p] + g_sums[2 + p]) * SCALE);
    out[0] = eg + w[NPARTS] * ek;
}

// ---------------------------------------------------------------------------
extern "C" void kernel_launch(void* const* d_in, const int* in_sizes, int n_in,
                              void* d_out, int out_size) {
    const float* cam  = (const float*)d_in[0];
    const float* cad  = (const float*)d_in[1];
    const float* w    = (const float*)d_in[2];
    const float* quat = (const float*)d_in[3];
    const float* tra  = (const float*)d_in[4];
    const float* jax_ = (const float*)d_in[5];
    float* out = (float*)d_out;

    k_pack<<<128, 256>>>(cam, cad, quat, tra);
    k_chamfer<<<NBLOCKS, TPB>>>();
    k_reduce<<<32, 256>>>();
    k_final<<<1, 64>>>(w, quat, tra, jax_, out, out_size);
}